// round 14
// baseline (speedup 1.0000x reference)
#include <cuda_runtime.h>
#include <cuda_bf16.h>
#include <cstdint>
#include <math.h>

#define BATCH 2
#define NT    2048
#define NSEG1 1536
#define NSEG2 512
#define DM    1024
#define NH    16
#define HD    64
#define KP    3072      // gemm split-K: [hi | hi | lo] (A)  /  [hi | lo | hi] (B)
#define GLD   144       // gemm smem row stride bytes (64 bf16 + 16B pad)

typedef unsigned long long u64;
typedef unsigned int u32;

// ---------------- scratch (static, no allocation) ----------------
static __device__ float g_qkv[BATCH * NT * 3 * DM];

// bf16 hi/lo attention operands (b, h, n, d)
static __device__ __nv_bfloat16 g_qh[BATCH * NH * NT * HD], g_ql[BATCH * NH * NT * HD];
static __device__ __nv_bfloat16 g_kh[BATCH * NH * NT * HD], g_kl[BATCH * NH * NT * HD];
static __device__ __nv_bfloat16 g_vh[BATCH * NH * NT * HD], g_vl[BATCH * NH * NT * HD];

// bf16 split buffers for GEMMs: [rows][3072]
static __device__ __nv_bfloat16 g_a1[3072 * KP];
static __device__ __nv_bfloat16 g_a2[1024 * KP];
static __device__ __nv_bfloat16 g_x2[4096 * KP];
static __device__ __nv_bfloat16 g_w1[3072 * KP];
static __device__ __nv_bfloat16 g_w2[3072 * KP];
static __device__ __nv_bfloat16 g_o1[1024 * KP];
static __device__ __nv_bfloat16 g_o2[1024 * KP];

// ---------------- small helpers ----------------
__device__ __forceinline__ void cp16(u32 saddr, const void* gptr) {
    asm volatile("cp.async.ca.shared.global [%0], [%1], 16;" :: "r"(saddr), "l"(gptr));
}
__device__ __forceinline__ void cp_commit() { asm volatile("cp.async.commit_group;"); }
__device__ __forceinline__ void cp_wait1() { asm volatile("cp.async.wait_group 1;"); }
__device__ __forceinline__ void cp_wait0() { asm volatile("cp.async.wait_group 0;"); }

__device__ __forceinline__ float fexp(float x) {
    x = fmaxf(x, -80.0f);
    float t = x * 1.4426950408889634f;
    float n = rintf(t);
    float f = t - n;
    float z = f * 0.6931471805599453f;
    float p = 1.0f + z * (1.0f + z * (0.5f + z * (0.16666667f + z * (0.041666667f + z * 0.008333334f))));
    int ni = (int)n;
    float s = __int_as_float((ni + 127) << 23);
    return p * s;
}

__device__ __forceinline__ void ldsm4(u32* d, u32 addr) {
    asm volatile("ldmatrix.sync.aligned.m8n8.x4.shared.b16 {%0,%1,%2,%3}, [%4];"
                 : "=r"(d[0]), "=r"(d[1]), "=r"(d[2]), "=r"(d[3]) : "r"(addr));
}
__device__ __forceinline__ void ldsm4t(u32* d, u32 addr) {
    asm volatile("ldmatrix.sync.aligned.m8n8.x4.trans.shared.b16 {%0,%1,%2,%3}, [%4];"
                 : "=r"(d[0]), "=r"(d[1]), "=r"(d[2]), "=r"(d[3]) : "r"(addr));
}
__device__ __forceinline__ void mma16816(float* c, const u32* a, const u32* b) {
    asm volatile(
        "mma.sync.aligned.m16n8k16.row.col.f32.bf16.bf16.f32 "
        "{%0,%1,%2,%3}, {%4,%5,%6,%7}, {%8,%9}, {%0,%1,%2,%3};"
        : "+f"(c[0]), "+f"(c[1]), "+f"(c[2]), "+f"(c[3])
        : "r"(a[0]), "r"(a[1]), "r"(a[2]), "r"(a[3]), "r"(b[0]), "r"(b[1]));
}

// pack two fp32 into bf16x2 (lo half = p0) and residual bf16x2
__device__ __forceinline__ void split_pack(float p0, float p1, u32& hi, u32& lo) {
    u32 hp;
    asm("cvt.rn.bf16x2.f32 %0, %1, %2;" : "=r"(hp) : "f"(p1), "f"(p0));
    float r0 = p0 - __uint_as_float(hp << 16);
    float r1 = p1 - __uint_as_float(hp & 0xFFFF0000u);
    u32 lp;
    asm("cvt.rn.bf16x2.f32 %0, %1, %2;" : "=r"(lp) : "f"(r1), "f"(r0));
    hi = hp; lo = lp;
}

// ---------------------------------------------------------------------------
// ALL six fp32 -> bf16 split conversions in ONE launch (round-13 verified).
// ---------------------------------------------------------------------------
#define CS0 786432            // x1  (3072 rows)
#define CS1 (CS0 + 262144)    // x2  (1024 rows)
#define CS2 (CS1 + 786432)    // Wq1 (3072 rows)
#define CS3 (CS2 + 786432)    // Wq2 (3072 rows)
#define CS4 (CS3 + 262144)    // Wo1 (1024 rows)
#define CS5 (CS4 + 262144)    // Wo2 (1024 rows)

__global__ void __launch_bounds__(256)
cvt_all(const float4* __restrict__ x1, const float4* __restrict__ x2,
        const float4* __restrict__ Wq1, const float4* __restrict__ Wq2,
        const float4* __restrict__ Wo1, const float4* __restrict__ Wo2,
        __nv_bfloat16* __restrict__ a1, __nv_bfloat16* __restrict__ a2,
        __nv_bfloat16* __restrict__ w1, __nv_bfloat16* __restrict__ w2,
        __nv_bfloat16* __restrict__ o1, __nv_bfloat16* __restrict__ o2)
{
    for (int g = blockIdx.x * blockDim.x + threadIdx.x; g < CS5;
         g += gridDim.x * blockDim.x) {
        const float4* src;
        __nv_bfloat16* dst;
        int i, mode;
        if (g < CS1) {
            mode = 0;
            if (g < CS0) { src = x1; dst = a1; i = g; }
            else         { src = x2; dst = a2; i = g - CS0; }
        } else {
            mode = 1;
            if (g < CS2)      { src = Wq1; dst = w1; i = g - CS1; }
            else if (g < CS3) { src = Wq2; dst = w2; i = g - CS2; }
            else if (g < CS4) { src = Wo1; dst = o1; i = g - CS3; }
            else              { src = Wo2; dst = o2; i = g - CS4; }
        }

        float4 v = src[i];
        int row = i >> 8;
        int c = (i & 255) * 4;
        u32 h01, l01, h23, l23;
        split_pack(v.x, v.y, h01, l01);
        split_pack(v.z, v.w, h23, l23);
        uint2 hv = make_uint2(h01, h23);
        uint2 lv = make_uint2(l01, l23);
        __nv_bfloat16* base = dst + (long long)row * KP + c;
        *(uint2*)(base) = hv;
        if (mode == 0) {
            *(uint2*)(base + 1024) = hv;
            *(uint2*)(base + 2048) = lv;
        } else {
            *(uint2*)(base + 1024) = lv;
            *(uint2*)(base + 2048) = hv;
        }
    }
}

// ---------------------------------------------------------------------------
// bf16 mma.sync GEMM (round-11 verified), two segments per launch.
// ---------------------------------------------------------------------------
#define GSMEM (2 * 2 * 128 * GLD)

__global__ void __launch_bounds__(256, 2)
gemm_mma2(const __nv_bfloat16* __restrict__ A0, const __nv_bfloat16* __restrict__ B0,
          const float* __restrict__ bias0, float* __restrict__ C0,
          int aRPB0, int aSTR0, int cRPB0, long long cBS0,
          const __nv_bfloat16* __restrict__ A1, const __nv_bfloat16* __restrict__ B1,
          const float* __restrict__ bias1, float* __restrict__ C1,
          int aRPB1, int aSTR1, int cRPB1, long long cBS1,
          int N, int mSplit)
{
    extern __shared__ __align__(16) char gsm[];

    const int tid = threadIdx.x;
    const int wid = tid >> 5;
    const int lane = tid & 31;
    const int wm = wid >> 2;
    const int wn = wid & 3;
    const int n0 = blockIdx.x * 128;

    const __nv_bfloat16 *A, *B;
    const float* bias;
    float* C;
    int aRPB, aSTR, cRPB;
    long long cBS;
    int m0;
    if ((int)blockIdx.y < mSplit) {
        A = A0; B = B0; bias = bias0; C = C0;
        aRPB = aRPB0; aSTR = aSTR0; cRPB = cRPB0; cBS = cBS0;
        m0 = blockIdx.y * 128;
    } else {
        A = A1; B = B1; bias = bias1; C = C1;
        aRPB = aRPB1; aSTR = aSTR1; cRPB = cRPB1; cBS = cBS1;
        m0 = (blockIdx.y - mSplit) * 128;
    }

    const u32 smem_base = (u32)__cvta_generic_to_shared(gsm);
    const u32 sA0 = smem_base;
    const u32 sB0 = smem_base + 128 * GLD;
    const u32 bufstride = 2 * 128 * GLD;

    const int r = tid >> 1;
    const int hf = tid & 1;
    int am = m0 + r;
    int ab = am / aRPB;
    const __nv_bfloat16* asrc = A + ((long long)ab * aSTR + (am - ab * aRPB)) * KP + hf * 32;
    const __nv_bfloat16* bsrc = B + (long long)(n0 + r) * KP + hf * 32;
    const u32 dstoff = r * GLD + hf * 64;

    const u32 aoff = (lane & 15) * GLD + (lane >> 4) * 16;
    const u32 boff = ((lane & 7) + ((lane >> 4) << 3)) * GLD + ((lane >> 3) & 1) * 16;

    float acc[4][4][4];
#pragma unroll
    for (int i = 0; i < 4; i++)
#pragma unroll
        for (int j = 0; j < 4; j++)
#pragma unroll
            for (int q = 0; q < 4; q++) acc[i][j][q] = 0.0f;

#pragma unroll
    for (int j = 0; j < 4; j++) {
        cp16(sA0 + dstoff + 16 * j, asrc + 8 * j);
        cp16(sB0 + dstoff + 16 * j, bsrc + 8 * j);
    }
    cp_commit();

    const int nIter = KP / 64;
    for (int it = 0; it < nIter; ++it) {
        const int s = it & 1;
        __syncthreads();

        if (it + 1 < nIter) {
            const int k0 = (it + 1) * 64;
            const u32 d = ((it + 1) & 1) * bufstride;
#pragma unroll
            for (int j = 0; j < 4; j++) {
                cp16(sA0 + d + dstoff + 16 * j, asrc + k0 + 8 * j);
                cp16(sB0 + d + dstoff + 16 * j, bsrc + k0 + 8 * j);
            }
            cp_commit();
            cp_wait1();
        } else {
            cp_wait0();
        }
        __syncthreads();

        const u32 sA = sA0 + s * bufstride;
        const u32 sB = sB0 + s * bufstride;
#pragma unroll
        for (int ks = 0; ks < 4; ks++) {
            u32 af[4][4], bf[2][4];
#pragma unroll
            for (int mt = 0; mt < 4; mt++)
                ldsm4(af[mt], sA + (wm * 64 + mt * 16) * GLD + aoff + ks * 32);
#pragma unroll
            for (int np = 0; np < 2; np++)
                ldsm4(bf[np], sB + (wn * 32 + np * 16) * GLD + boff + ks * 32);
#pragma unroll
            for (int mt = 0; mt < 4; mt++) {
#pragma unroll
                for (int nt = 0; nt < 4; nt++)
                    mma16816(acc[mt][nt], af[mt], bf[nt >> 1] + (nt & 1) * 2);
            }
        }
    }

#pragma unroll
    for (int mt = 0; mt < 4; mt++) {
        int row0 = m0 + wm * 64 + mt * 16 + (lane >> 2);
#pragma unroll
        for (int half_m = 0; half_m < 2; half_m++) {
            int row = row0 + half_m * 8;
            int cb = row / cRPB;
            float* crow = C + (long long)cb * cBS + (long long)(row - cb * cRPB) * N;
#pragma unroll
            for (int nt = 0; nt < 4; nt++) {
                int col = n0 + wn * 32 + nt * 8 + 2 * (lane & 3);
                float2 b2 = *(const float2*)(bias + col);
                float2 o = make_float2(acc[mt][nt][2 * half_m] + b2.x,
                                       acc[mt][nt][2 * half_m + 1] + b2.y);
                *(float2*)(crow + col) = o;
            }
        }
    }
}

// ---------------------------------------------------------------------------
// Split QKV + RMSNorm + RoPE -> bf16 hi/lo operand buffers.
// ---------------------------------------------------------------------------
__global__ void __launch_bounds__(256)
qkv_post(const float* __restrict__ qs1, const float* __restrict__ ks1,
         const float* __restrict__ qs2, const float* __restrict__ ks2)
{
    int w = (blockIdx.x * blockDim.x + threadIdx.x) >> 5;
    int lane = threadIdx.x & 31;
    int h = w & 15;
    int n = (w >> 4) & (NT - 1);
    int b = w >> 15;

    const float* row = g_qkv + (long long)(b * NT + n) * (3 * DM);
    const float* qs = (n < NSEG1) ? qs1 : qs2;
    const float* ks = (n < NSEG1) ? ks1 : ks2;

    float pos = (float)n;
    float e = (float)(2 * lane) * (1.0f / 64.0f);
    float invf = expf(-e * 9.210340371976184f);
    float ang = pos * invf;
    float cs = cosf(ang), sn = sinf(ang);

    long long obase = ((long long)(b * NH + h) * NT + n) * HD + 2 * lane;
    int doff = h * HD + 2 * lane;

    // Q (scaled 1/8)
    {
        float2 v = *(const float2*)(row + doff);
        float ss = v.x * v.x + v.y * v.y;
#pragma unroll
        for (int off = 16; off; off >>= 1) ss += __shfl_xor_sync(0xffffffffu, ss, off);
        float inv = rsqrtf(ss * (1.0f / 64.0f) + 1e-6f);
        float a = v.x * inv * qs[2 * lane];
        float c = v.y * inv * qs[2 * lane + 1];
        float ox = (a * cs - c * sn) * 0.125f;
        float oy = (a * sn + c * cs) * 0.125f;
        u32 hp, lp;
        split_pack(ox, oy, hp, lp);
        *(u32*)(g_qh + obase) = hp;
        *(u32*)(g_ql + obase) = lp;
    }
    // K
    {
        float2 v = *(const float2*)(row + DM + doff);
        float ss = v.x * v.x + v.y * v.y;
#pragma unroll
        for (int off = 16; off; off >>= 1) ss += __shfl_xor_sync(0xffffffffu, ss, off);
        float inv = rsqrtf(ss * (1.0f / 64.0f) + 1e-6f);
        float a = v.x * inv * ks[2 * lane];
        float c = v.y * inv * ks[2 * lane + 1];
        float ox = a * cs - c * sn;
        float oy = a * sn + c * cs;
        u32 hp, lp;
        split_pack(ox, oy, hp, lp);
        *(u32*)(g_kh + obase) = hp;
        *(u32*)(g_kl + obase) = lp;
    }
    // V
    {
        float2 v = *(const float2*)(row + 2 * DM + doff);
        u32 hp, lp;
        split_pack(v.x, v.y, hp, lp);
        *(u32*)(g_vh + obase) = hp;
        *(u32*)(g_vl + obase) = lp;
    }
}

// ---------------------------------------------------------------------------
// Flash attention on the tensor pipe. Identical structure to round-13 EXCEPT
// the mma issue order inside the S and PV loops now alternates independent
// accumulators (dep distance 2 instead of back-to-back RAW chains of 3).
// ---------------------------------------------------------------------------
#define FTILE 18432                    // 128 rows x 144 B
#define FSQH  0
#define FSQL  FTILE
#define FSKV  (2 * FTILE)
#define FBUF  (4 * FTILE)
#define FA_SMEM (FSKV + 2 * FBUF)      // 184320 B

__global__ void __launch_bounds__(256, 1)
flash_attn()
{
    extern __shared__ char smx[];
    const u32 sbase = (u32)__cvta_generic_to_shared(smx);
    const int b = blockIdx.z, h = blockIdx.y;
    const int q0 = blockIdx.x * 128;
    const int tid = threadIdx.x;
    const int w = tid >> 5;
    const int lane = tid & 31;

    const long long bh = (long long)(b * NH + h) * NT;

    const int r = tid >> 1;
    const int hf = tid & 1;
    const u32 ldst = r * 144 + hf * 64;
    const __nv_bfloat16* qh_s = g_qh + (bh + q0 + r) * HD + hf * 32;
    const __nv_bfloat16* ql_s = g_ql + (bh + q0 + r) * HD + hf * 32;
    const __nv_bfloat16* kh_s = g_kh + (bh + r) * HD + hf * 32;
    const __nv_bfloat16* kl_s = g_kl + (bh + r) * HD + hf * 32;
    const __nv_bfloat16* vh_s = g_vh + (bh + r) * HD + hf * 32;
    const __nv_bfloat16* vl_s = g_vl + (bh + r) * HD + hf * 32;

#pragma unroll
    for (int j = 0; j < 4; j++) {
        cp16(sbase + FSQH + ldst + 16 * j, qh_s + 8 * j);
        cp16(sbase + FSQL + ldst + 16 * j, ql_s + 8 * j);
    }
    cp_commit();
#pragma unroll
    for (int j = 0; j < 4; j++) {
        cp16(sbase + FSKV + 0 * FTILE + ldst + 16 * j, kh_s + 8 * j);
        cp16(sbase + FSKV + 1 * FTILE + ldst + 16 * j, kl_s + 8 * j);
        cp16(sbase + FSKV + 2 * FTILE + ldst + 16 * j, vh_s + 8 * j);
        cp16(sbase + FSKV + 3 * FTILE + ldst + 16 * j, vl_s + 8 * j);
    }
    cp_commit();

    const u32 aoff = (lane & 15) * 144 + (lane >> 4) * 16;
    const u32 boff = ((lane & 7) + ((lane >> 4) << 3)) * 144 + ((lane >> 3) & 1) * 16;
    const u32 voff = ((lane & 7) + ((lane >> 3) & 1) * 8) * 144 + (lane >> 4) * 16;

    u32 qfh[4][4], qfl[4][4];
    float o[8][4];
    float m0 = -1e30f, m1 = -1e30f, l0 = 0.0f, l1 = 0.0f;
#pragma unroll
    for (int i = 0; i < 8; i++)
#pragma unroll
        for (int q = 0; q < 4; q++) o[i][q] = 0.0f;

    const int nTiles = NT / 128;
    for (int t = 0; t < nTiles; ++t) {
        const int s = t & 1;

        if (t + 1 < nTiles) {
            const long long roff = (long long)(t + 1) * 128 * HD;
            const u32 dbuf = sbase + FSKV + ((t + 1) & 1) * FBUF;
#pragma unroll
            for (int j = 0; j < 4; j++) {
                cp16(dbuf + 0 * FTILE + ldst + 16 * j, kh_s + roff + 8 * j);
                cp16(dbuf + 1 * FTILE + ldst + 16 * j, kl_s + roff + 8 * j);
                cp16(dbuf + 2 * FTILE + ldst + 16 * j, vh_s + roff + 8 * j);
                cp16(dbuf + 3 * FTILE + ldst + 16 * j, vl_s + roff + 8 * j);
            }
            cp_commit();
            cp_wait1();
        } else {
            cp_wait0();
        }
        __syncthreads();

        if (t == 0) {
            const u32 qbh = sbase + FSQH + w * 16 * 144;
            const u32 qbl = sbase + FSQL + w * 16 * 144;
#pragma unroll
            for (int kc = 0; kc < 4; kc++) {
                ldsm4(qfh[kc], qbh + kc * 32 + aoff);
                ldsm4(qfl[kc], qbl + kc * 32 + aoff);
            }
        }

        const u32 skh = sbase + FSKV + s * FBUF;
        const u32 skl = skh + FTILE;
        const u32 svh = skh + 2 * FTILE;
        const u32 svl = skh + 3 * FTILE;

        // ---- S = Q K^T (interleaved accumulators: dep distance 2) ----
        float sc[16][4];
#pragma unroll
        for (int nt = 0; nt < 16; nt++)
#pragma unroll
            for (int q = 0; q < 4; q++) sc[nt][q] = 0.0f;

#pragma unroll
        for (int np = 0; np < 8; np++) {
#pragma unroll
            for (int kc = 0; kc < 4; kc++) {
                u32 bh4[4], bl4[4];
                ldsm4(bh4, skh + np * 16 * 144 + kc * 32 + boff);
                ldsm4(bl4, skl + np * 16 * 144 + kc * 32 + boff);
                mma16816(sc[2 * np],     qfh[kc], bh4);
                mma16816(sc[2 * np + 1], qfh[kc], bh4 + 2);
                mma16816(sc[2 * np],     qfl[kc], bh4);
                mma16816(sc[2 * np + 1], qfl[kc], bh4 + 2);
                mma16816(sc[2 * np],     qfh[kc], bl4);
                mma16816(sc[2 * np + 1], qfh[kc], bl4 + 2);
            }
        }

        // ---- online softmax ----
        float mt0 = sc[0][0], mt1 = sc[0][2];
#pragma unroll
        for (int nt = 0; nt < 16; nt++) {
            mt0 = fmaxf(mt0, fmaxf(sc[nt][0], sc[nt][1]));
            mt1 = fmaxf(mt1, fmaxf(sc[nt][2], sc[nt][3]));
        }
        mt0 = fmaxf(mt0, __shfl_xor_sync(0xffffffffu, mt0, 1));
        mt0 = fmaxf(mt0, __shfl_xor_sync(0xffffffffu, mt0, 2));
        mt1 = fmaxf(mt1, __shfl_xor_sync(0xffffffffu, mt1, 1));
        mt1 = fmaxf(mt1, __shfl_xor_sync(0xffffffffu, mt1, 2));
        float nm0 = fmaxf(m0, mt0), nm1 = fmaxf(m1, mt1);
        float f0 = fexp(m0 - nm0), f1 = fexp(m1 - nm1);
        m0 = nm0; m1 = nm1;

        float ts0 = 0.0f, ts1 = 0.0f;
#pragma unroll
        for (int nt = 0; nt < 16; nt++) {
            sc[nt][0] = fexp(sc[nt][0] - nm0);
            sc[nt][1] = fexp(sc[nt][1] - nm0);
            sc[nt][2] = fexp(sc[nt][2] - nm1);
            sc[nt][3] = fexp(sc[nt][3] - nm1);
            ts0 += sc[nt][0] + sc[nt][1];
            ts1 += sc[nt][2] + sc[nt][3];
        }
        ts0 += __shfl_xor_sync(0xffffffffu, ts0, 1);
        ts0 += __shfl_xor_sync(0xffffffffu, ts0, 2);
        ts1 += __shfl_xor_sync(0xffffffffu, ts1, 1);
        ts1 += __shfl_xor_sync(0xffffffffu, ts1, 2);
        l0 = l0 * f0 + ts0;
        l1 = l1 * f1 + ts1;

#pragma unroll
        for (int nt = 0; nt < 8; nt++) {
            o[nt][0] *= f0; o[nt][1] *= f0;
            o[nt][2] *= f1; o[nt][3] *= f1;
        }

        // ---- O += P V (interleaved accumulators) ----
#pragma unroll
        for (int kc = 0; kc < 8; kc++) {
            u32 ah[4], al[4];
            split_pack(sc[2 * kc][0],     sc[2 * kc][1],     ah[0], al[0]);
            split_pack(sc[2 * kc][2],     sc[2 * kc][3],     ah[1], al[1]);
            split_pack(sc[2 * kc + 1][0], sc[2 * kc + 1][1], ah[2], al[2]);
            split_pack(sc[2 * kc + 1][2], sc[2 * kc + 1][3], ah[3], al[3]);
#pragma unroll
            for (int vp = 0; vp < 4; vp++) {
                u32 vh4[4], vl4[4];
                ldsm4t(vh4, svh + kc * 16 * 144 + vp * 32 + voff);
                ldsm4t(vl4, svl + kc * 16 * 144 + vp * 32 + voff);
                mma16816(o[2 * vp],     ah, vh4);
                mma16816(o[2 * vp + 1], ah, vh4 + 2);
                mma16816(o[2 * vp],     al, vh4);
                mma16816(o[2 * vp + 1], al, vh4 + 2);
                mma16816(o[2 * vp],     ah, vl4);
                mma16816(o[2 * vp + 1], ah, vl4 + 2);
            }
        }
        __syncthreads();
    }

    // ---- finalize: write split [hi|hi|lo] x2 buffer directly ----
    float inv0 = 1.0f / l0, inv1 = 1.0f / l1;
    int r0g = q0 + w * 16 + (lane >> 2);
    long long row0 = (long long)b * NT + r0g;
    __nv_bfloat16* p0 = g_x2 + row0 * KP;
    __nv_bfloat16* p1 = g_x2 + (row0 + 8) * KP;
    int cbase = h * HD + 2 * (lane & 3);
#pragma unroll
    for (int nt = 0; nt < 8; nt++) {
        int c = cbase + 8 * nt;
        u32 hp, lp;
        split_pack(o[nt][0] * inv0, o[nt][1] * inv0, hp, lp);
        *(u32*)(p0 + c) = hp;
        *(u32*)(p0 + 1024 + c) = hp;
        *(u32*)(p0 + 2048 + c) = lp;
        split_pack(o[nt][2] * inv1, o[nt][3] * inv1, hp, lp);
        *(u32*)(p1 + c) = hp;
        *(u32*)(p1 + 1024 + c) = hp;
        *(u32*)(p1 + 2048 + c) = lp;
    }
}

// ---------------------------------------------------------------------------
// Launch
// ---------------------------------------------------------------------------
extern "C" void kernel_launch(void* const* d_in, const int* in_sizes, int n_in,
                              void* d_out, int out_size)
{
    const float* x1  = (const float*)d_in[0];
    const float* x2  = (const float*)d_in[1];
    const float* Wq1 = (const float*)d_in[2];
    const float* bq1 = (const float*)d_in[3];
    const float* Wq2 = (const float*)d_in[4];
    const float* bq2 = (const float*)d_in[5];
    const float* Wo1 = (const float*)d_in[6];
    const float* bo1 = (const float*)d_in[7];
    const float* Wo2 = (const float*)d_in[8];
    const float* bo2 = (const float*)d_in[9];
    const float* qs1 = (const float*)d_in[10];
    const float* ks1 = (const float*)d_in[11];
    const float* qs2 = (const float*)d_in[12];
    const float* ks2 = (const float*)d_in[13];
    float* out = (float*)d_out;

    float* qkv;
    cudaGetSymbolAddress((void**)&qkv, g_qkv);
    __nv_bfloat16 *a1, *a2, *x2b, *w1, *w2, *o1, *o2;
    cudaGetSymbolAddress((void**)&a1, g_a1);
    cudaGetSymbolAddress((void**)&a2, g_a2);
    cudaGetSymbolAddress((void**)&x2b, g_x2);
    cudaGetSymbolAddress((void**)&w1, g_w1);
    cudaGetSymbolAddress((void**)&w2, g_w2);
    cudaGetSymbolAddress((void**)&o1, g_o1);
    cudaGetSymbolAddress((void**)&o2, g_o2);

    cudaFuncSetAttribute(flash_attn, cudaFuncAttributeMaxDynamicSharedMemorySize,
                         FA_SMEM);
    cudaFuncSetAttribute(gemm_mma2, cudaFuncAttributeMaxDynamicSharedMemorySize,
                         GSMEM);

    // --- ALL bf16 split conversions in one launch ---
    cvt_all<<<2048, 256>>>((const float4*)x1, (const float4*)x2,
                           (const float4*)Wq1, (const float4*)Wq2,
                           (const float4*)Wo1, (const float4*)Wo2,
                           a1, a2, w1, w2, o1, o2);

    // --- QKV projections, both segments in ONE launch ---
    gemm_mma2<<<dim3(24, 32), 256, GSMEM>>>(
        a1, w1, bq1, qkv,
        3072, 3072, NSEG1, (long long)NT * 3 * DM,
        a2, w2, bq2, qkv + (long long)NSEG1 * 3 * DM,
        1024, 1024, NSEG2, (long long)NT * 3 * DM,
        3072, 24);

    // --- split + RMSNorm + RoPE -> bf16 hi/lo operands ---
    qkv_post<<<(BATCH * NT * NH) / 8, 256>>>(qs1, ks1, qs2, ks2);

    // --- attention (tensor pipe), writes split x2 buffer directly ---
    flash_attn<<<dim3(NT / 128, NH, BATCH), 256, FA_SMEM>>>();

    // --- output projections, both segments in ONE launch ---
    gemm_mma2<<<dim3(8, 32), 256, GSMEM>>>(
        x2b, o1, bo1, out,
        1536, 2048, NSEG1, (long long)NSEG1 * DM,
        x2b + (long long)NSEG1 * KP, o2, bo2, out + (long long)BATCH * NSEG1 * DM,
        512, 2048, NSEG2, (long long)NSEG2 * DM,
        1024, 24);
}

// round 15
// speedup vs baseline: 1.0700x; 1.0700x over previous
#include <cuda_runtime.h>
#include <cuda_bf16.h>
#include <cstdint>
#include <math.h>

#define BATCH 2
#define NT    2048
#define NSEG1 1536
#define NSEG2 512
#define DM    1024
#define NH    16
#define HD    64
#define KP    3072      // gemm split-K: [hi | hi | lo] (A)  /  [hi | lo | hi] (B)
#define GLD   144       // gemm smem row stride bytes (64 bf16 + 16B pad)

typedef unsigned long long u64;
typedef unsigned int u32;

// ---------------- scratch (static, no allocation) ----------------
static __device__ float g_qkv[BATCH * NT * 3 * DM];

// bf16 hi/lo attention operands (b, h, n, d)
static __device__ __nv_bfloat16 g_qh[BATCH * NH * NT * HD], g_ql[BATCH * NH * NT * HD];
static __device__ __nv_bfloat16 g_kh[BATCH * NH * NT * HD], g_kl[BATCH * NH * NT * HD];
static __device__ __nv_bfloat16 g_vh[BATCH * NH * NT * HD], g_vl[BATCH * NH * NT * HD];

// split-KV partials: [b][h][half][qtile] x (128 rows x 64 cols) O, 128 l
static __device__ float g_po[BATCH * NH * 2 * 16 * 128 * 64];
static __device__ float g_pl[BATCH * NH * 2 * 16 * 128];

// bf16 split buffers for GEMMs: [rows][3072]
static __device__ __nv_bfloat16 g_a1[3072 * KP];
static __device__ __nv_bfloat16 g_a2[1024 * KP];
static __device__ __nv_bfloat16 g_x2[4096 * KP];
static __device__ __nv_bfloat16 g_w1[3072 * KP];
static __device__ __nv_bfloat16 g_w2[3072 * KP];
static __device__ __nv_bfloat16 g_o1[1024 * KP];
static __device__ __nv_bfloat16 g_o2[1024 * KP];

// ---------------- small helpers ----------------
__device__ __forceinline__ void cp16(u32 saddr, const void* gptr) {
    asm volatile("cp.async.ca.shared.global [%0], [%1], 16;" :: "r"(saddr), "l"(gptr));
}
__device__ __forceinline__ void cp_commit() { asm volatile("cp.async.commit_group;"); }
__device__ __forceinline__ void cp_wait1() { asm volatile("cp.async.wait_group 1;"); }
__device__ __forceinline__ void cp_wait0() { asm volatile("cp.async.wait_group 0;"); }

__device__ __forceinline__ float fexp(float x) {
    x = fmaxf(x, -80.0f);
    float t = x * 1.4426950408889634f;
    float n = rintf(t);
    float f = t - n;
    float z = f * 0.6931471805599453f;
    float p = 1.0f + z * (1.0f + z * (0.5f + z * (0.16666667f + z * (0.041666667f + z * 0.008333334f))));
    int ni = (int)n;
    float s = __int_as_float((ni + 127) << 23);
    return p * s;
}

__device__ __forceinline__ void ldsm4(u32* d, u32 addr) {
    asm volatile("ldmatrix.sync.aligned.m8n8.x4.shared.b16 {%0,%1,%2,%3}, [%4];"
                 : "=r"(d[0]), "=r"(d[1]), "=r"(d[2]), "=r"(d[3]) : "r"(addr));
}
__device__ __forceinline__ void ldsm4t(u32* d, u32 addr) {
    asm volatile("ldmatrix.sync.aligned.m8n8.x4.trans.shared.b16 {%0,%1,%2,%3}, [%4];"
                 : "=r"(d[0]), "=r"(d[1]), "=r"(d[2]), "=r"(d[3]) : "r"(addr));
}
__device__ __forceinline__ void mma16816(float* c, const u32* a, const u32* b) {
    asm volatile(
        "mma.sync.aligned.m16n8k16.row.col.f32.bf16.bf16.f32 "
        "{%0,%1,%2,%3}, {%4,%5,%6,%7}, {%8,%9}, {%0,%1,%2,%3};"
        : "+f"(c[0]), "+f"(c[1]), "+f"(c[2]), "+f"(c[3])
        : "r"(a[0]), "r"(a[1]), "r"(a[2]), "r"(a[3]), "r"(b[0]), "r"(b[1]));
}

// pack two fp32 into bf16x2 (lo half = p0) and residual bf16x2
__device__ __forceinline__ void split_pack(float p0, float p1, u32& hi, u32& lo) {
    u32 hp;
    asm("cvt.rn.bf16x2.f32 %0, %1, %2;" : "=r"(hp) : "f"(p1), "f"(p0));
    float r0 = p0 - __uint_as_float(hp << 16);
    float r1 = p1 - __uint_as_float(hp & 0xFFFF0000u);
    u32 lp;
    asm("cvt.rn.bf16x2.f32 %0, %1, %2;" : "=r"(lp) : "f"(r1), "f"(r0));
    hi = hp; lo = lp;
}

// ---------------------------------------------------------------------------
// ALL six fp32 -> bf16 split conversions in ONE launch (round-13 verified).
// ---------------------------------------------------------------------------
#define CS0 786432            // x1  (3072 rows)
#define CS1 (CS0 + 262144)    // x2  (1024 rows)
#define CS2 (CS1 + 786432)    // Wq1 (3072 rows)
#define CS3 (CS2 + 786432)    // Wq2 (3072 rows)
#define CS4 (CS3 + 262144)    // Wo1 (1024 rows)
#define CS5 (CS4 + 262144)    // Wo2 (1024 rows)

__global__ void __launch_bounds__(256)
cvt_all(const float4* __restrict__ x1, const float4* __restrict__ x2,
        const float4* __restrict__ Wq1, const float4* __restrict__ Wq2,
        const float4* __restrict__ Wo1, const float4* __restrict__ Wo2,
        __nv_bfloat16* __restrict__ a1, __nv_bfloat16* __restrict__ a2,
        __nv_bfloat16* __restrict__ w1, __nv_bfloat16* __restrict__ w2,
        __nv_bfloat16* __restrict__ o1, __nv_bfloat16* __restrict__ o2)
{
    for (int g = blockIdx.x * blockDim.x + threadIdx.x; g < CS5;
         g += gridDim.x * blockDim.x) {
        const float4* src;
        __nv_bfloat16* dst;
        int i, mode;
        if (g < CS1) {
            mode = 0;
            if (g < CS0) { src = x1; dst = a1; i = g; }
            else         { src = x2; dst = a2; i = g - CS0; }
        } else {
            mode = 1;
            if (g < CS2)      { src = Wq1; dst = w1; i = g - CS1; }
            else if (g < CS3) { src = Wq2; dst = w2; i = g - CS2; }
            else if (g < CS4) { src = Wo1; dst = o1; i = g - CS3; }
            else              { src = Wo2; dst = o2; i = g - CS4; }
        }

        float4 v = src[i];
        int row = i >> 8;
        int c = (i & 255) * 4;
        u32 h01, l01, h23, l23;
        split_pack(v.x, v.y, h01, l01);
        split_pack(v.z, v.w, h23, l23);
        uint2 hv = make_uint2(h01, h23);
        uint2 lv = make_uint2(l01, l23);
        __nv_bfloat16* base = dst + (long long)row * KP + c;
        *(uint2*)(base) = hv;
        if (mode == 0) {
            *(uint2*)(base + 1024) = hv;
            *(uint2*)(base + 2048) = lv;
        } else {
            *(uint2*)(base + 1024) = lv;
            *(uint2*)(base + 2048) = hv;
        }
    }
}

// ---------------------------------------------------------------------------
// bf16 mma.sync GEMM (round-11 verified), two segments per launch.
// ---------------------------------------------------------------------------
#define GSMEM (2 * 2 * 128 * GLD)

__global__ void __launch_bounds__(256, 2)
gemm_mma2(const __nv_bfloat16* __restrict__ A0, const __nv_bfloat16* __restrict__ B0,
          const float* __restrict__ bias0, float* __restrict__ C0,
          int aRPB0, int aSTR0, int cRPB0, long long cBS0,
          const __nv_bfloat16* __restrict__ A1, const __nv_bfloat16* __restrict__ B1,
          const float* __restrict__ bias1, float* __restrict__ C1,
          int aRPB1, int aSTR1, int cRPB1, long long cBS1,
          int N, int mSplit)
{
    extern __shared__ __align__(16) char gsm[];

    const int tid = threadIdx.x;
    const int wid = tid >> 5;
    const int lane = tid & 31;
    const int wm = wid >> 2;
    const int wn = wid & 3;
    const int n0 = blockIdx.x * 128;

    const __nv_bfloat16 *A, *B;
    const float* bias;
    float* C;
    int aRPB, aSTR, cRPB;
    long long cBS;
    int m0;
    if ((int)blockIdx.y < mSplit) {
        A = A0; B = B0; bias = bias0; C = C0;
        aRPB = aRPB0; aSTR = aSTR0; cRPB = cRPB0; cBS = cBS0;
        m0 = blockIdx.y * 128;
    } else {
        A = A1; B = B1; bias = bias1; C = C1;
        aRPB = aRPB1; aSTR = aSTR1; cRPB = cRPB1; cBS = cBS1;
        m0 = (blockIdx.y - mSplit) * 128;
    }

    const u32 smem_base = (u32)__cvta_generic_to_shared(gsm);
    const u32 sA0 = smem_base;
    const u32 sB0 = smem_base + 128 * GLD;
    const u32 bufstride = 2 * 128 * GLD;

    const int r = tid >> 1;
    const int hf = tid & 1;
    int am = m0 + r;
    int ab = am / aRPB;
    const __nv_bfloat16* asrc = A + ((long long)ab * aSTR + (am - ab * aRPB)) * KP + hf * 32;
    const __nv_bfloat16* bsrc = B + (long long)(n0 + r) * KP + hf * 32;
    const u32 dstoff = r * GLD + hf * 64;

    const u32 aoff = (lane & 15) * GLD + (lane >> 4) * 16;
    const u32 boff = ((lane & 7) + ((lane >> 4) << 3)) * GLD + ((lane >> 3) & 1) * 16;

    float acc[4][4][4];
#pragma unroll
    for (int i = 0; i < 4; i++)
#pragma unroll
        for (int j = 0; j < 4; j++)
#pragma unroll
            for (int q = 0; q < 4; q++) acc[i][j][q] = 0.0f;

#pragma unroll
    for (int j = 0; j < 4; j++) {
        cp16(sA0 + dstoff + 16 * j, asrc + 8 * j);
        cp16(sB0 + dstoff + 16 * j, bsrc + 8 * j);
    }
    cp_commit();

    const int nIter = KP / 64;
    for (int it = 0; it < nIter; ++it) {
        const int s = it & 1;
        __syncthreads();

        if (it + 1 < nIter) {
            const int k0 = (it + 1) * 64;
            const u32 d = ((it + 1) & 1) * bufstride;
#pragma unroll
            for (int j = 0; j < 4; j++) {
                cp16(sA0 + d + dstoff + 16 * j, asrc + k0 + 8 * j);
                cp16(sB0 + d + dstoff + 16 * j, bsrc + k0 + 8 * j);
            }
            cp_commit();
            cp_wait1();
        } else {
            cp_wait0();
        }
        __syncthreads();

        const u32 sA = sA0 + s * bufstride;
        const u32 sB = sB0 + s * bufstride;
#pragma unroll
        for (int ks = 0; ks < 4; ks++) {
            u32 af[4][4], bf[2][4];
#pragma unroll
            for (int mt = 0; mt < 4; mt++)
                ldsm4(af[mt], sA + (wm * 64 + mt * 16) * GLD + aoff + ks * 32);
#pragma unroll
            for (int np = 0; np < 2; np++)
                ldsm4(bf[np], sB + (wn * 32 + np * 16) * GLD + boff + ks * 32);
#pragma unroll
            for (int mt = 0; mt < 4; mt++) {
#pragma unroll
                for (int nt = 0; nt < 4; nt++)
                    mma16816(acc[mt][nt], af[mt], bf[nt >> 1] + (nt & 1) * 2);
            }
        }
    }

#pragma unroll
    for (int mt = 0; mt < 4; mt++) {
        int row0 = m0 + wm * 64 + mt * 16 + (lane >> 2);
#pragma unroll
        for (int half_m = 0; half_m < 2; half_m++) {
            int row = row0 + half_m * 8;
            int cb = row / cRPB;
            float* crow = C + (long long)cb * cBS + (long long)(row - cb * cRPB) * N;
#pragma unroll
            for (int nt = 0; nt < 4; nt++) {
                int col = n0 + wn * 32 + nt * 8 + 2 * (lane & 3);
                float2 b2 = *(const float2*)(bias + col);
                float2 o = make_float2(acc[mt][nt][2 * half_m] + b2.x,
                                       acc[mt][nt][2 * half_m + 1] + b2.y);
                *(float2*)(crow + col) = o;
            }
        }
    }
}

// ---------------------------------------------------------------------------
// Split QKV + RMSNorm + RoPE -> bf16 hi/lo operand buffers.
// ---------------------------------------------------------------------------
__global__ void __launch_bounds__(256)
qkv_post(const float* __restrict__ qs1, const float* __restrict__ ks1,
         const float* __restrict__ qs2, const float* __restrict__ ks2)
{
    int w = (blockIdx.x * blockDim.x + threadIdx.x) >> 5;
    int lane = threadIdx.x & 31;
    int h = w & 15;
    int n = (w >> 4) & (NT - 1);
    int b = w >> 15;

    const float* row = g_qkv + (long long)(b * NT + n) * (3 * DM);
    const float* qs = (n < NSEG1) ? qs1 : qs2;
    const float* ks = (n < NSEG1) ? ks1 : ks2;

    float pos = (float)n;
    float e = (float)(2 * lane) * (1.0f / 64.0f);
    float invf = expf(-e * 9.210340371976184f);
    float ang = pos * invf;
    float cs = cosf(ang), sn = sinf(ang);

    long long obase = ((long long)(b * NH + h) * NT + n) * HD + 2 * lane;
    int doff = h * HD + 2 * lane;

    // Q (scaled 1/8)
    {
        float2 v = *(const float2*)(row + doff);
        float ss = v.x * v.x + v.y * v.y;
#pragma unroll
        for (int off = 16; off; off >>= 1) ss += __shfl_xor_sync(0xffffffffu, ss, off);
        float inv = rsqrtf(ss * (1.0f / 64.0f) + 1e-6f);
        float a = v.x * inv * qs[2 * lane];
        float c = v.y * inv * qs[2 * lane + 1];
        float ox = (a * cs - c * sn) * 0.125f;
        float oy = (a * sn + c * cs) * 0.125f;
        u32 hp, lp;
        split_pack(ox, oy, hp, lp);
        *(u32*)(g_qh + obase) = hp;
        *(u32*)(g_ql + obase) = lp;
    }
    // K
    {
        float2 v = *(const float2*)(row + DM + doff);
        float ss = v.x * v.x + v.y * v.y;
#pragma unroll
        for (int off = 16; off; off >>= 1) ss += __shfl_xor_sync(0xffffffffu, ss, off);
        float inv = rsqrtf(ss * (1.0f / 64.0f) + 1e-6f);
        float a = v.x * inv * ks[2 * lane];
        float c = v.y * inv * ks[2 * lane + 1];
        float ox = a * cs - c * sn;
        float oy = a * sn + c * cs;
        u32 hp, lp;
        split_pack(ox, oy, hp, lp);
        *(u32*)(g_kh + obase) = hp;
        *(u32*)(g_kl + obase) = lp;
    }
    // V
    {
        float2 v = *(const float2*)(row + 2 * DM + doff);
        u32 hp, lp;
        split_pack(v.x, v.y, hp, lp);
        *(u32*)(g_vh + obase) = hp;
        *(u32*)(g_vl + obase) = lp;
    }
}

// ---------------------------------------------------------------------------
// Flash attention, split-KV (2 halves) + fixed-max softmax.
// RMSNorm bounds |q|,|k| < 8 => scores = qk/8 < 8, so P = exp(s - 8) needs
// no running max, no rescale; l is a deferred thread-local sum.
// Each CTA: 128 q-rows x 1024 keys (half). Partial O (fp32) + l to scratch.
// ---------------------------------------------------------------------------
#define FTILE 18432                    // 128 rows x 144 B
#define FSQH  0
#define FSQL  FTILE
#define FSKV  (2 * FTILE)
#define FBUF  (4 * FTILE)
#define FA_SMEM (FSKV + 2 * FBUF)      // 184320 B

__global__ void __launch_bounds__(256, 1)
flash_attn()
{
    extern __shared__ char smx[];
    const u32 sbase = (u32)__cvta_generic_to_shared(smx);
    const int qt = blockIdx.x;
    const int h = blockIdx.y;
    const int b = blockIdx.z & 1;
    const int half = blockIdx.z >> 1;
    const int q0 = qt * 128;
    const int tid = threadIdx.x;
    const int w = tid >> 5;
    const int lane = tid & 31;

    const long long bh = (long long)(b * NH + h) * NT;
    const long long koff = (long long)half * 1024;

    const int r = tid >> 1;
    const int hf = tid & 1;
    const u32 ldst = r * 144 + hf * 64;
    const __nv_bfloat16* qh_s = g_qh + (bh + q0 + r) * HD + hf * 32;
    const __nv_bfloat16* ql_s = g_ql + (bh + q0 + r) * HD + hf * 32;
    const __nv_bfloat16* kh_s = g_kh + (bh + koff + r) * HD + hf * 32;
    const __nv_bfloat16* kl_s = g_kl + (bh + koff + r) * HD + hf * 32;
    const __nv_bfloat16* vh_s = g_vh + (bh + koff + r) * HD + hf * 32;
    const __nv_bfloat16* vl_s = g_vl + (bh + koff + r) * HD + hf * 32;

#pragma unroll
    for (int j = 0; j < 4; j++) {
        cp16(sbase + FSQH + ldst + 16 * j, qh_s + 8 * j);
        cp16(sbase + FSQL + ldst + 16 * j, ql_s + 8 * j);
    }
    cp_commit();
#pragma unroll
    for (int j = 0; j < 4; j++) {
        cp16(sbase + FSKV + 0 * FTILE + ldst + 16 * j, kh_s + 8 * j);
        cp16(sbase + FSKV + 1 * FTILE + ldst + 16 * j, kl_s + 8 * j);
        cp16(sbase + FSKV + 2 * FTILE + ldst + 16 * j, vh_s + 8 * j);
        cp16(sbase + FSKV + 3 * FTILE + ldst + 16 * j, vl_s + 8 * j);
    }
    cp_commit();

    const u32 aoff = (lane & 15) * 144 + (lane >> 4) * 16;
    const u32 boff = ((lane & 7) + ((lane >> 4) << 3)) * 144 + ((lane >> 3) & 1) * 16;
    const u32 voff = ((lane & 7) + ((lane >> 3) & 1) * 8) * 144 + (lane >> 4) * 16;

    u32 qfh[4][4], qfl[4][4];
    float o[8][4];
    float l0 = 0.0f, l1 = 0.0f;
#pragma unroll
    for (int i = 0; i < 8; i++)
#pragma unroll
        for (int q = 0; q < 4; q++) o[i][q] = 0.0f;

    const int nTiles = 1024 / 128;   // 8 tiles in this half
    for (int t = 0; t < nTiles; ++t) {
        const int s = t & 1;

        if (t + 1 < nTiles) {
            const long long roff = (long long)(t + 1) * 128 * HD;
            const u32 dbuf = sbase + FSKV + ((t + 1) & 1) * FBUF;
#pragma unroll
            for (int j = 0; j < 4; j++) {
                cp16(dbuf + 0 * FTILE + ldst + 16 * j, kh_s + roff + 8 * j);
                cp16(dbuf + 1 * FTILE + ldst + 16 * j, kl_s + roff + 8 * j);
                cp16(dbuf + 2 * FTILE + ldst + 16 * j, vh_s + roff + 8 * j);
                cp16(dbuf + 3 * FTILE + ldst + 16 * j, vl_s + roff + 8 * j);
            }
            cp_commit();
            cp_wait1();
        } else {
            cp_wait0();
        }
        __syncthreads();

        if (t == 0) {
            const u32 qbh = sbase + FSQH + w * 16 * 144;
            const u32 qbl = sbase + FSQL + w * 16 * 144;
#pragma unroll
            for (int kc = 0; kc < 4; kc++) {
                ldsm4(qfh[kc], qbh + kc * 32 + aoff);
                ldsm4(qfl[kc], qbl + kc * 32 + aoff);
            }
        }

        const u32 skh = sbase + FSKV + s * FBUF;
        const u32 skl = skh + FTILE;
        const u32 svh = skh + 2 * FTILE;
        const u32 svl = skh + 3 * FTILE;

        // ---- S = Q K^T ----
        float sc[16][4];
#pragma unroll
        for (int nt = 0; nt < 16; nt++)
#pragma unroll
            for (int q = 0; q < 4; q++) sc[nt][q] = 0.0f;

#pragma unroll
        for (int np = 0; np < 8; np++) {
#pragma unroll
            for (int kc = 0; kc < 4; kc++) {
                u32 bh4[4], bl4[4];
                ldsm4(bh4, skh + np * 16 * 144 + kc * 32 + boff);
                ldsm4(bl4, skl + np * 16 * 144 + kc * 32 + boff);
                mma16816(sc[2 * np],     qfh[kc], bh4);
                mma16816(sc[2 * np + 1], qfh[kc], bh4 + 2);
                mma16816(sc[2 * np],     qfl[kc], bh4);
                mma16816(sc[2 * np + 1], qfl[kc], bh4 + 2);
                mma16816(sc[2 * np],     qfh[kc], bl4);
                mma16816(sc[2 * np + 1], qfh[kc], bl4 + 2);
            }
        }

        // ---- fixed-max softmax: P = exp(s - 8), no max/rescale ----
#pragma unroll
        for (int nt = 0; nt < 16; nt++) {
            sc[nt][0] = fexp(sc[nt][0] - 8.0f);
            sc[nt][1] = fexp(sc[nt][1] - 8.0f);
            sc[nt][2] = fexp(sc[nt][2] - 8.0f);
            sc[nt][3] = fexp(sc[nt][3] - 8.0f);
            l0 += sc[nt][0] + sc[nt][1];
            l1 += sc[nt][2] + sc[nt][3];
        }

        // ---- O += P V ----
#pragma unroll
        for (int kc = 0; kc < 8; kc++) {
            u32 ah[4], al[4];
            split_pack(sc[2 * kc][0],     sc[2 * kc][1],     ah[0], al[0]);
            split_pack(sc[2 * kc][2],     sc[2 * kc][3],     ah[1], al[1]);
            split_pack(sc[2 * kc + 1][0], sc[2 * kc + 1][1], ah[2], al[2]);
            split_pack(sc[2 * kc + 1][2], sc[2 * kc + 1][3], ah[3], al[3]);
#pragma unroll
            for (int vp = 0; vp < 4; vp++) {
                u32 vh4[4], vl4[4];
                ldsm4t(vh4, svh + kc * 16 * 144 + vp * 32 + voff);
                ldsm4t(vl4, svl + kc * 16 * 144 + vp * 32 + voff);
                mma16816(o[2 * vp],     ah, vh4);
                mma16816(o[2 * vp + 1], ah, vh4 + 2);
                mma16816(o[2 * vp],     al, vh4);
                mma16816(o[2 * vp + 1], al, vh4 + 2);
                mma16816(o[2 * vp],     ah, vl4);
                mma16816(o[2 * vp + 1], ah, vl4 + 2);
            }
        }
        __syncthreads();
    }

    // ---- write partial O (fp32) and l ----
    l0 += __shfl_xor_sync(0xffffffffu, l0, 1);
    l0 += __shfl_xor_sync(0xffffffffu, l0, 2);
    l1 += __shfl_xor_sync(0xffffffffu, l1, 1);
    l1 += __shfl_xor_sync(0xffffffffu, l1, 2);

    const long long pidx = (((long long)(b * NH + h)) * 2 + half) * 16 + qt;
    float* PO = g_po + pidx * (128 * 64);
    int r0 = w * 16 + (lane >> 2);
    int cc = 2 * (lane & 3);
#pragma unroll
    for (int nt = 0; nt < 8; nt++) {
        *(float2*)(PO + r0 * 64 + 8 * nt + cc) = make_float2(o[nt][0], o[nt][1]);
        *(float2*)(PO + (r0 + 8) * 64 + 8 * nt + cc) = make_float2(o[nt][2], o[nt][3]);
    }
    if ((lane & 3) == 0) {
        g_pl[pidx * 128 + r0] = l0;
        g_pl[pidx * 128 + r0 + 8] = l1;
    }
}

// ---------------------------------------------------------------------------
// Merge the two KV halves: x = (O0 + O1) / (l0 + l1), write split x2 buffer.
// One thread per (b, n, h, col-pair): 2*2048*16*32 = 2.1M threads.
// ---------------------------------------------------------------------------
__global__ void __launch_bounds__(256)
merge_attn()
{
    int g = blockIdx.x * blockDim.x + threadIdx.x;
    int cp = g & 31;              // col pair 0..31
    int h = (g >> 5) & 15;
    int n = (g >> 9) & 2047;
    int b = g >> 20;
    int qt = n >> 7;
    int lr = n & 127;

    long long p0i = (((long long)(b * NH + h)) * 2 + 0) * 16 + qt;
    long long p1i = p0i + 16;     // half=1
    const float2 O0 = *(const float2*)(g_po + p0i * (128 * 64) + lr * 64 + 2 * cp);
    const float2 O1 = *(const float2*)(g_po + p1i * (128 * 64) + lr * 64 + 2 * cp);
    float l = g_pl[p0i * 128 + lr] + g_pl[p1i * 128 + lr];
    float inv = 1.0f / l;
    float ox = (O0.x + O1.x) * inv;
    float oy = (O0.y + O1.y) * inv;

    u32 hp, lp;
    split_pack(ox, oy, hp, lp);
    __nv_bfloat16* dst = g_x2 + ((long long)b * NT + n) * KP + h * HD + 2 * cp;
    *(u32*)(dst) = hp;
    *(u32*)(dst + 1024) = hp;
    *(u32*)(dst + 2048) = lp;
}

// ---------------------------------------------------------------------------
// Launch
// ---------------------------------------------------------------------------
extern "C" void kernel_launch(void* const* d_in, const int* in_sizes, int n_in,
                              void* d_out, int out_size)
{
    const float* x1  = (const float*)d_in[0];
    const float* x2  = (const float*)d_in[1];
    const float* Wq1 = (const float*)d_in[2];
    const float* bq1 = (const float*)d_in[3];
    const float* Wq2 = (const float*)d_in[4];
    const float* bq2 = (const float*)d_in[5];
    const float* Wo1 = (const float*)d_in[6];
    const float* bo1 = (const float*)d_in[7];
    const float* Wo2 = (const float*)d_in[8];
    const float* bo2 = (const float*)d_in[9];
    const float* qs1 = (const float*)d_in[10];
    const float* ks1 = (const float*)d_in[11];
    const float* qs2 = (const float*)d_in[12];
    const float* ks2 = (const float*)d_in[13];
    float* out = (float*)d_out;

    float* qkv;
    cudaGetSymbolAddress((void**)&qkv, g_qkv);
    __nv_bfloat16 *a1, *a2, *x2b, *w1, *w2, *o1, *o2;
    cudaGetSymbolAddress((void**)&a1, g_a1);
    cudaGetSymbolAddress((void**)&a2, g_a2);
    cudaGetSymbolAddress((void**)&x2b, g_x2);
    cudaGetSymbolAddress((void**)&w1, g_w1);
    cudaGetSymbolAddress((void**)&w2, g_w2);
    cudaGetSymbolAddress((void**)&o1, g_o1);
    cudaGetSymbolAddress((void**)&o2, g_o2);

    cudaFuncSetAttribute(flash_attn, cudaFuncAttributeMaxDynamicSharedMemorySize,
                         FA_SMEM);
    cudaFuncSetAttribute(gemm_mma2, cudaFuncAttributeMaxDynamicSharedMemorySize,
                         GSMEM);

    // --- ALL bf16 split conversions in one launch ---
    cvt_all<<<2048, 256>>>((const float4*)x1, (const float4*)x2,
                           (const float4*)Wq1, (const float4*)Wq2,
                           (const float4*)Wo1, (const float4*)Wo2,
                           a1, a2, w1, w2, o1, o2);

    // --- QKV projections, both segments in ONE launch ---
    gemm_mma2<<<dim3(24, 32), 256, GSMEM>>>(
        a1, w1, bq1, qkv,
        3072, 3072, NSEG1, (long long)NT * 3 * DM,
        a2, w2, bq2, qkv + (long long)NSEG1 * 3 * DM,
        1024, 1024, NSEG2, (long long)NT * 3 * DM,
        3072, 24);

    // --- split + RMSNorm + RoPE -> bf16 hi/lo operands ---
    qkv_post<<<(BATCH * NT * NH) / 8, 256>>>(qs1, ks1, qs2, ks2);

    // --- attention: split-KV partials, then merge ---
    flash_attn<<<dim3(16, NH, BATCH * 2), 256, FA_SMEM>>>();
    merge_attn<<<(BATCH * NT * NH * 32) / 256, 256>>>();

    // --- output projections, both segments in ONE launch ---
    gemm_mma2<<<dim3(8, 32), 256, GSMEM>>>(
        x2b, o1, bo1, out,
        1536, 2048, NSEG1, (long long)NSEG1 * DM,
        x2b + (long long)NSEG1 * KP, o2, bo2, out + (long long)BATCH * NSEG1 * DM,
        512, 2048, NSEG2, (long long)NSEG2 * DM,
        1024, 24);
}

// round 16
// speedup vs baseline: 1.1208x; 1.0474x over previous
#include <cuda_runtime.h>
#include <cuda_bf16.h>
#include <cstdint>
#include <math.h>

#define BATCH 2
#define NT    2048
#define NSEG1 1536
#define NSEG2 512
#define DM    1024
#define NH    16
#define HD    64
#define KP    3072      // gemm split-K: [hi | hi | lo] (A)  /  [hi | lo | hi] (B)
#define GLD   144       // gemm smem row stride bytes (64 bf16 + 16B pad)

typedef unsigned long long u64;
typedef unsigned int u32;

// ---------------- scratch (static, no allocation) ----------------
static __device__ float g_qkv[BATCH * NT * 3 * DM];

// bf16 hi/lo attention operands (b, h, n, d)
static __device__ __nv_bfloat16 g_qh[BATCH * NH * NT * HD], g_ql[BATCH * NH * NT * HD];
static __device__ __nv_bfloat16 g_kh[BATCH * NH * NT * HD], g_kl[BATCH * NH * NT * HD];
static __device__ __nv_bfloat16 g_vh[BATCH * NH * NT * HD], g_vl[BATCH * NH * NT * HD];

// split-KV partials: [b][h][half][qtile] x (128 rows x 64 cols) O, 128 l
static __device__ float g_po[BATCH * NH * 2 * 16 * 128 * 64];
static __device__ float g_pl[BATCH * NH * 2 * 16 * 128];

// bf16 split buffers for GEMMs: [rows][3072]
static __device__ __nv_bfloat16 g_a1[3072 * KP];
static __device__ __nv_bfloat16 g_a2[1024 * KP];
static __device__ __nv_bfloat16 g_x2[4096 * KP];
static __device__ __nv_bfloat16 g_w1[3072 * KP];
static __device__ __nv_bfloat16 g_w2[3072 * KP];
static __device__ __nv_bfloat16 g_o1[1024 * KP];
static __device__ __nv_bfloat16 g_o2[1024 * KP];

// ---------------- small helpers ----------------
__device__ __forceinline__ void cp16(u32 saddr, const void* gptr) {
    asm volatile("cp.async.ca.shared.global [%0], [%1], 16;" :: "r"(saddr), "l"(gptr));
}
__device__ __forceinline__ void cp_commit() { asm volatile("cp.async.commit_group;"); }
__device__ __forceinline__ void cp_wait1() { asm volatile("cp.async.wait_group 1;"); }
__device__ __forceinline__ void cp_wait0() { asm volatile("cp.async.wait_group 0;"); }

__device__ __forceinline__ float fexp(float x) {
    x = fmaxf(x, -80.0f);
    float t = x * 1.4426950408889634f;
    float n = rintf(t);
    float f = t - n;
    float z = f * 0.6931471805599453f;
    float p = 1.0f + z * (1.0f + z * (0.5f + z * (0.16666667f + z * (0.041666667f + z * 0.008333334f))));
    int ni = (int)n;
    float s = __int_as_float((ni + 127) << 23);
    return p * s;
}

// exp(s - 8) via MUFU: 1 FFMA + 1 ex2.approx. Valid for -8 <= s <= 8.
__device__ __forceinline__ float fexp8(float s) {
    float r;
    float t = fmaf(s, 1.4426950408889634f, -11.541560327111708f);
    asm("ex2.approx.f32 %0, %1;" : "=f"(r) : "f"(t));
    return r;
}

__device__ __forceinline__ void ldsm4(u32* d, u32 addr) {
    asm volatile("ldmatrix.sync.aligned.m8n8.x4.shared.b16 {%0,%1,%2,%3}, [%4];"
                 : "=r"(d[0]), "=r"(d[1]), "=r"(d[2]), "=r"(d[3]) : "r"(addr));
}
__device__ __forceinline__ void ldsm4t(u32* d, u32 addr) {
    asm volatile("ldmatrix.sync.aligned.m8n8.x4.trans.shared.b16 {%0,%1,%2,%3}, [%4];"
                 : "=r"(d[0]), "=r"(d[1]), "=r"(d[2]), "=r"(d[3]) : "r"(addr));
}
__device__ __forceinline__ void mma16816(float* c, const u32* a, const u32* b) {
    asm volatile(
        "mma.sync.aligned.m16n8k16.row.col.f32.bf16.bf16.f32 "
        "{%0,%1,%2,%3}, {%4,%5,%6,%7}, {%8,%9}, {%0,%1,%2,%3};"
        : "+f"(c[0]), "+f"(c[1]), "+f"(c[2]), "+f"(c[3])
        : "r"(a[0]), "r"(a[1]), "r"(a[2]), "r"(a[3]), "r"(b[0]), "r"(b[1]));
}

// pack two fp32 into bf16x2 (lo half = p0) and residual bf16x2
__device__ __forceinline__ void split_pack(float p0, float p1, u32& hi, u32& lo) {
    u32 hp;
    asm("cvt.rn.bf16x2.f32 %0, %1, %2;" : "=r"(hp) : "f"(p1), "f"(p0));
    float r0 = p0 - __uint_as_float(hp << 16);
    float r1 = p1 - __uint_as_float(hp & 0xFFFF0000u);
    u32 lp;
    asm("cvt.rn.bf16x2.f32 %0, %1, %2;" : "=r"(lp) : "f"(r1), "f"(r0));
    hi = hp; lo = lp;
}

// ---------------------------------------------------------------------------
// ALL six fp32 -> bf16 split conversions in ONE launch (round-13 verified).
// ---------------------------------------------------------------------------
#define CS0 786432            // x1  (3072 rows)
#define CS1 (CS0 + 262144)    // x2  (1024 rows)
#define CS2 (CS1 + 786432)    // Wq1 (3072 rows)
#define CS3 (CS2 + 786432)    // Wq2 (3072 rows)
#define CS4 (CS3 + 262144)    // Wo1 (1024 rows)
#define CS5 (CS4 + 262144)    // Wo2 (1024 rows)

__global__ void __launch_bounds__(256)
cvt_all(const float4* __restrict__ x1, const float4* __restrict__ x2,
        const float4* __restrict__ Wq1, const float4* __restrict__ Wq2,
        const float4* __restrict__ Wo1, const float4* __restrict__ Wo2,
        __nv_bfloat16* __restrict__ a1, __nv_bfloat16* __restrict__ a2,
        __nv_bfloat16* __restrict__ w1, __nv_bfloat16* __restrict__ w2,
        __nv_bfloat16* __restrict__ o1, __nv_bfloat16* __restrict__ o2)
{
    for (int g = blockIdx.x * blockDim.x + threadIdx.x; g < CS5;
         g += gridDim.x * blockDim.x) {
        const float4* src;
        __nv_bfloat16* dst;
        int i, mode;
        if (g < CS1) {
            mode = 0;
            if (g < CS0) { src = x1; dst = a1; i = g; }
            else         { src = x2; dst = a2; i = g - CS0; }
        } else {
            mode = 1;
            if (g < CS2)      { src = Wq1; dst = w1; i = g - CS1; }
            else if (g < CS3) { src = Wq2; dst = w2; i = g - CS2; }
            else if (g < CS4) { src = Wo1; dst = o1; i = g - CS3; }
            else              { src = Wo2; dst = o2; i = g - CS4; }
        }

        float4 v = src[i];
        int row = i >> 8;
        int c = (i & 255) * 4;
        u32 h01, l01, h23, l23;
        split_pack(v.x, v.y, h01, l01);
        split_pack(v.z, v.w, h23, l23);
        uint2 hv = make_uint2(h01, h23);
        uint2 lv = make_uint2(l01, l23);
        __nv_bfloat16* base = dst + (long long)row * KP + c;
        *(uint2*)(base) = hv;
        if (mode == 0) {
            *(uint2*)(base + 1024) = hv;
            *(uint2*)(base + 2048) = lv;
        } else {
            *(uint2*)(base + 1024) = lv;
            *(uint2*)(base + 2048) = hv;
        }
    }
}

// ---------------------------------------------------------------------------
// bf16 mma.sync GEMM (round-11 verified), two segments per launch.
// ---------------------------------------------------------------------------
#define GSMEM (2 * 2 * 128 * GLD)

__global__ void __launch_bounds__(256, 2)
gemm_mma2(const __nv_bfloat16* __restrict__ A0, const __nv_bfloat16* __restrict__ B0,
          const float* __restrict__ bias0, float* __restrict__ C0,
          int aRPB0, int aSTR0, int cRPB0, long long cBS0,
          const __nv_bfloat16* __restrict__ A1, const __nv_bfloat16* __restrict__ B1,
          const float* __restrict__ bias1, float* __restrict__ C1,
          int aRPB1, int aSTR1, int cRPB1, long long cBS1,
          int N, int mSplit)
{
    extern __shared__ __align__(16) char gsm[];

    const int tid = threadIdx.x;
    const int wid = tid >> 5;
    const int lane = tid & 31;
    const int wm = wid >> 2;
    const int wn = wid & 3;
    const int n0 = blockIdx.x * 128;

    const __nv_bfloat16 *A, *B;
    const float* bias;
    float* C;
    int aRPB, aSTR, cRPB;
    long long cBS;
    int m0;
    if ((int)blockIdx.y < mSplit) {
        A = A0; B = B0; bias = bias0; C = C0;
        aRPB = aRPB0; aSTR = aSTR0; cRPB = cRPB0; cBS = cBS0;
        m0 = blockIdx.y * 128;
    } else {
        A = A1; B = B1; bias = bias1; C = C1;
        aRPB = aRPB1; aSTR = aSTR1; cRPB = cRPB1; cBS = cBS1;
        m0 = (blockIdx.y - mSplit) * 128;
    }

    const u32 smem_base = (u32)__cvta_generic_to_shared(gsm);
    const u32 sA0 = smem_base;
    const u32 sB0 = smem_base + 128 * GLD;
    const u32 bufstride = 2 * 128 * GLD;

    const int r = tid >> 1;
    const int hf = tid & 1;
    int am = m0 + r;
    int ab = am / aRPB;
    const __nv_bfloat16* asrc = A + ((long long)ab * aSTR + (am - ab * aRPB)) * KP + hf * 32;
    const __nv_bfloat16* bsrc = B + (long long)(n0 + r) * KP + hf * 32;
    const u32 dstoff = r * GLD + hf * 64;

    const u32 aoff = (lane & 15) * GLD + (lane >> 4) * 16;
    const u32 boff = ((lane & 7) + ((lane >> 4) << 3)) * GLD + ((lane >> 3) & 1) * 16;

    float acc[4][4][4];
#pragma unroll
    for (int i = 0; i < 4; i++)
#pragma unroll
        for (int j = 0; j < 4; j++)
#pragma unroll
            for (int q = 0; q < 4; q++) acc[i][j][q] = 0.0f;

#pragma unroll
    for (int j = 0; j < 4; j++) {
        cp16(sA0 + dstoff + 16 * j, asrc + 8 * j);
        cp16(sB0 + dstoff + 16 * j, bsrc + 8 * j);
    }
    cp_commit();

    const int nIter = KP / 64;
    for (int it = 0; it < nIter; ++it) {
        const int s = it & 1;
        __syncthreads();

        if (it + 1 < nIter) {
            const int k0 = (it + 1) * 64;
            const u32 d = ((it + 1) & 1) * bufstride;
#pragma unroll
            for (int j = 0; j < 4; j++) {
                cp16(sA0 + d + dstoff + 16 * j, asrc + k0 + 8 * j);
                cp16(sB0 + d + dstoff + 16 * j, bsrc + k0 + 8 * j);
            }
            cp_commit();
            cp_wait1();
        } else {
            cp_wait0();
        }
        __syncthreads();

        const u32 sA = sA0 + s * bufstride;
        const u32 sB = sB0 + s * bufstride;
#pragma unroll
        for (int ks = 0; ks < 4; ks++) {
            u32 af[4][4], bf[2][4];
#pragma unroll
            for (int mt = 0; mt < 4; mt++)
                ldsm4(af[mt], sA + (wm * 64 + mt * 16) * GLD + aoff + ks * 32);
#pragma unroll
            for (int np = 0; np < 2; np++)
                ldsm4(bf[np], sB + (wn * 32 + np * 16) * GLD + boff + ks * 32);
#pragma unroll
            for (int mt = 0; mt < 4; mt++) {
#pragma unroll
                for (int nt = 0; nt < 4; nt++)
                    mma16816(acc[mt][nt], af[mt], bf[nt >> 1] + (nt & 1) * 2);
            }
        }
    }

#pragma unroll
    for (int mt = 0; mt < 4; mt++) {
        int row0 = m0 + wm * 64 + mt * 16 + (lane >> 2);
#pragma unroll
        for (int half_m = 0; half_m < 2; half_m++) {
            int row = row0 + half_m * 8;
            int cb = row / cRPB;
            float* crow = C + (long long)cb * cBS + (long long)(row - cb * cRPB) * N;
#pragma unroll
            for (int nt = 0; nt < 4; nt++) {
                int col = n0 + wn * 32 + nt * 8 + 2 * (lane & 3);
                float2 b2 = *(const float2*)(bias + col);
                float2 o = make_float2(acc[mt][nt][2 * half_m] + b2.x,
                                       acc[mt][nt][2 * half_m + 1] + b2.y);
                *(float2*)(crow + col) = o;
            }
        }
    }
}

// ---------------------------------------------------------------------------
// Split QKV + RMSNorm + RoPE -> bf16 hi/lo operand buffers.
// ---------------------------------------------------------------------------
__global__ void __launch_bounds__(256)
qkv_post(const float* __restrict__ qs1, const float* __restrict__ ks1,
         const float* __restrict__ qs2, const float* __restrict__ ks2)
{
    int w = (blockIdx.x * blockDim.x + threadIdx.x) >> 5;
    int lane = threadIdx.x & 31;
    int h = w & 15;
    int n = (w >> 4) & (NT - 1);
    int b = w >> 15;

    const float* row = g_qkv + (long long)(b * NT + n) * (3 * DM);
    const float* qs = (n < NSEG1) ? qs1 : qs2;
    const float* ks = (n < NSEG1) ? ks1 : ks2;

    float pos = (float)n;
    float e = (float)(2 * lane) * (1.0f / 64.0f);
    float invf = expf(-e * 9.210340371976184f);
    float ang = pos * invf;
    float cs = cosf(ang), sn = sinf(ang);

    long long obase = ((long long)(b * NH + h) * NT + n) * HD + 2 * lane;
    int doff = h * HD + 2 * lane;

    // Q (scaled 1/8)
    {
        float2 v = *(const float2*)(row + doff);
        float ss = v.x * v.x + v.y * v.y;
#pragma unroll
        for (int off = 16; off; off >>= 1) ss += __shfl_xor_sync(0xffffffffu, ss, off);
        float inv = rsqrtf(ss * (1.0f / 64.0f) + 1e-6f);
        float a = v.x * inv * qs[2 * lane];
        float c = v.y * inv * qs[2 * lane + 1];
        float ox = (a * cs - c * sn) * 0.125f;
        float oy = (a * sn + c * cs) * 0.125f;
        u32 hp, lp;
        split_pack(ox, oy, hp, lp);
        *(u32*)(g_qh + obase) = hp;
        *(u32*)(g_ql + obase) = lp;
    }
    // K
    {
        float2 v = *(const float2*)(row + DM + doff);
        float ss = v.x * v.x + v.y * v.y;
#pragma unroll
        for (int off = 16; off; off >>= 1) ss += __shfl_xor_sync(0xffffffffu, ss, off);
        float inv = rsqrtf(ss * (1.0f / 64.0f) + 1e-6f);
        float a = v.x * inv * ks[2 * lane];
        float c = v.y * inv * ks[2 * lane + 1];
        float ox = a * cs - c * sn;
        float oy = a * sn + c * cs;
        u32 hp, lp;
        split_pack(ox, oy, hp, lp);
        *(u32*)(g_kh + obase) = hp;
        *(u32*)(g_kl + obase) = lp;
    }
    // V
    {
        float2 v = *(const float2*)(row + 2 * DM + doff);
        u32 hp, lp;
        split_pack(v.x, v.y, hp, lp);
        *(u32*)(g_vh + obase) = hp;
        *(u32*)(g_vl + obase) = lp;
    }
}

// ---------------------------------------------------------------------------
// Flash attention, split-KV (2 halves) + fixed-max softmax with MUFU exp.
// P = exp(s - 8) = ex2(s*log2e - 8*log2e): 1 FFMA + 1 MUFU per score,
// freeing ~450 fma-pipe issue slots per tile per warp vs the polynomial.
// ---------------------------------------------------------------------------
#define FTILE 18432                    // 128 rows x 144 B
#define FSQH  0
#define FSQL  FTILE
#define FSKV  (2 * FTILE)
#define FBUF  (4 * FTILE)
#define FA_SMEM (FSKV + 2 * FBUF)      // 184320 B

__global__ void __launch_bounds__(256, 1)
flash_attn()
{
    extern __shared__ char smx[];
    const u32 sbase = (u32)__cvta_generic_to_shared(smx);
    const int qt = blockIdx.x;
    const int h = blockIdx.y;
    const int b = blockIdx.z & 1;
    const int half = blockIdx.z >> 1;
    const int q0 = qt * 128;
    const int tid = threadIdx.x;
    const int w = tid >> 5;
    const int lane = tid & 31;

    const long long bh = (long long)(b * NH + h) * NT;
    const long long koff = (long long)half * 1024;

    const int r = tid >> 1;
    const int hf = tid & 1;
    const u32 ldst = r * 144 + hf * 64;
    const __nv_bfloat16* qh_s = g_qh + (bh + q0 + r) * HD + hf * 32;
    const __nv_bfloat16* ql_s = g_ql + (bh + q0 + r) * HD + hf * 32;
    const __nv_bfloat16* kh_s = g_kh + (bh + koff + r) * HD + hf * 32;
    const __nv_bfloat16* kl_s = g_kl + (bh + koff + r) * HD + hf * 32;
    const __nv_bfloat16* vh_s = g_vh + (bh + koff + r) * HD + hf * 32;
    const __nv_bfloat16* vl_s = g_vl + (bh + koff + r) * HD + hf * 32;

#pragma unroll
    for (int j = 0; j < 4; j++) {
        cp16(sbase + FSQH + ldst + 16 * j, qh_s + 8 * j);
        cp16(sbase + FSQL + ldst + 16 * j, ql_s + 8 * j);
    }
    cp_commit();
#pragma unroll
    for (int j = 0; j < 4; j++) {
        cp16(sbase + FSKV + 0 * FTILE + ldst + 16 * j, kh_s + 8 * j);
        cp16(sbase + FSKV + 1 * FTILE + ldst + 16 * j, kl_s + 8 * j);
        cp16(sbase + FSKV + 2 * FTILE + ldst + 16 * j, vh_s + 8 * j);
        cp16(sbase + FSKV + 3 * FTILE + ldst + 16 * j, vl_s + 8 * j);
    }
    cp_commit();

    const u32 aoff = (lane & 15) * 144 + (lane >> 4) * 16;
    const u32 boff = ((lane & 7) + ((lane >> 4) << 3)) * 144 + ((lane >> 3) & 1) * 16;
    const u32 voff = ((lane & 7) + ((lane >> 3) & 1) * 8) * 144 + (lane >> 4) * 16;

    u32 qfh[4][4], qfl[4][4];
    float o[8][4];
    float l0 = 0.0f, l1 = 0.0f;
#pragma unroll
    for (int i = 0; i < 8; i++)
#pragma unroll
        for (int q = 0; q < 4; q++) o[i][q] = 0.0f;

    const int nTiles = 1024 / 128;   // 8 tiles in this half
    for (int t = 0; t < nTiles; ++t) {
        const int s = t & 1;

        if (t + 1 < nTiles) {
            const long long roff = (long long)(t + 1) * 128 * HD;
            const u32 dbuf = sbase + FSKV + ((t + 1) & 1) * FBUF;
#pragma unroll
            for (int j = 0; j < 4; j++) {
                cp16(dbuf + 0 * FTILE + ldst + 16 * j, kh_s + roff + 8 * j);
                cp16(dbuf + 1 * FTILE + ldst + 16 * j, kl_s + roff + 8 * j);
                cp16(dbuf + 2 * FTILE + ldst + 16 * j, vh_s + roff + 8 * j);
                cp16(dbuf + 3 * FTILE + ldst + 16 * j, vl_s + roff + 8 * j);
            }
            cp_commit();
            cp_wait1();
        } else {
            cp_wait0();
        }
        __syncthreads();

        if (t == 0) {
            const u32 qbh = sbase + FSQH + w * 16 * 144;
            const u32 qbl = sbase + FSQL + w * 16 * 144;
#pragma unroll
            for (int kc = 0; kc < 4; kc++) {
                ldsm4(qfh[kc], qbh + kc * 32 + aoff);
                ldsm4(qfl[kc], qbl + kc * 32 + aoff);
            }
        }

        const u32 skh = sbase + FSKV + s * FBUF;
        const u32 skl = skh + FTILE;
        const u32 svh = skh + 2 * FTILE;
        const u32 svl = skh + 3 * FTILE;

        // ---- S = Q K^T ----
        float sc[16][4];
#pragma unroll
        for (int nt = 0; nt < 16; nt++)
#pragma unroll
            for (int q = 0; q < 4; q++) sc[nt][q] = 0.0f;

#pragma unroll
        for (int np = 0; np < 8; np++) {
#pragma unroll
            for (int kc = 0; kc < 4; kc++) {
                u32 bh4[4], bl4[4];
                ldsm4(bh4, skh + np * 16 * 144 + kc * 32 + boff);
                ldsm4(bl4, skl + np * 16 * 144 + kc * 32 + boff);
                mma16816(sc[2 * np],     qfh[kc], bh4);
                mma16816(sc[2 * np + 1], qfh[kc], bh4 + 2);
                mma16816(sc[2 * np],     qfl[kc], bh4);
                mma16816(sc[2 * np + 1], qfl[kc], bh4 + 2);
                mma16816(sc[2 * np],     qfh[kc], bl4);
                mma16816(sc[2 * np + 1], qfh[kc], bl4 + 2);
            }
        }

        // ---- fixed-max softmax via MUFU: P = ex2(s*log2e - 8*log2e) ----
#pragma unroll
        for (int nt = 0; nt < 16; nt++) {
            sc[nt][0] = fexp8(sc[nt][0]);
            sc[nt][1] = fexp8(sc[nt][1]);
            sc[nt][2] = fexp8(sc[nt][2]);
            sc[nt][3] = fexp8(sc[nt][3]);
            l0 += sc[nt][0] + sc[nt][1];
            l1 += sc[nt][2] + sc[nt][3];
        }

        // ---- O += P V ----
#pragma unroll
        for (int kc = 0; kc < 8; kc++) {
            u32 ah[4], al[4];
            split_pack(sc[2 * kc][0],     sc[2 * kc][1],     ah[0], al[0]);
            split_pack(sc[2 * kc][2],     sc[2 * kc][3],     ah[1], al[1]);
            split_pack(sc[2 * kc + 1][0], sc[2 * kc + 1][1], ah[2], al[2]);
            split_pack(sc[2 * kc + 1][2], sc[2 * kc + 1][3], ah[3], al[3]);
#pragma unroll
            for (int vp = 0; vp < 4; vp++) {
                u32 vh4[4], vl4[4];
                ldsm4t(vh4, svh + kc * 16 * 144 + vp * 32 + voff);
                ldsm4t(vl4, svl + kc * 16 * 144 + vp * 32 + voff);
                mma16816(o[2 * vp],     ah, vh4);
                mma16816(o[2 * vp + 1], ah, vh4 + 2);
                mma16816(o[2 * vp],     al, vh4);
                mma16816(o[2 * vp + 1], al, vh4 + 2);
                mma16816(o[2 * vp],     ah, vl4);
                mma16816(o[2 * vp + 1], ah, vl4 + 2);
            }
        }
        __syncthreads();
    }

    // ---- write partial O (fp32) and l ----
    l0 += __shfl_xor_sync(0xffffffffu, l0, 1);
    l0 += __shfl_xor_sync(0xffffffffu, l0, 2);
    l1 += __shfl_xor_sync(0xffffffffu, l1, 1);
    l1 += __shfl_xor_sync(0xffffffffu, l1, 2);

    const long long pidx = (((long long)(b * NH + h)) * 2 + half) * 16 + qt;
    float* PO = g_po + pidx * (128 * 64);
    int r0 = w * 16 + (lane >> 2);
    int cc = 2 * (lane & 3);
#pragma unroll
    for (int nt = 0; nt < 8; nt++) {
        *(float2*)(PO + r0 * 64 + 8 * nt + cc) = make_float2(o[nt][0], o[nt][1]);
        *(float2*)(PO + (r0 + 8) * 64 + 8 * nt + cc) = make_float2(o[nt][2], o[nt][3]);
    }
    if ((lane & 3) == 0) {
        g_pl[pidx * 128 + r0] = l0;
        g_pl[pidx * 128 + r0 + 8] = l1;
    }
}

// ---------------------------------------------------------------------------
// Merge the two KV halves: x = (O0 + O1) / (l0 + l1), write split x2 buffer.
// ---------------------------------------------------------------------------
__global__ void __launch_bounds__(256)
merge_attn()
{
    int g = blockIdx.x * blockDim.x + threadIdx.x;
    int cp = g & 31;              // col pair 0..31
    int h = (g >> 5) & 15;
    int n = (g >> 9) & 2047;
    int b = g >> 20;
    int qt = n >> 7;
    int lr = n & 127;

    long long p0i = (((long long)(b * NH + h)) * 2 + 0) * 16 + qt;
    long long p1i = p0i + 16;     // half=1
    const float2 O0 = *(const float2*)(g_po + p0i * (128 * 64) + lr * 64 + 2 * cp);
    const float2 O1 = *(const float2*)(g_po + p1i * (128 * 64) + lr * 64 + 2 * cp);
    float l = g_pl[p0i * 128 + lr] + g_pl[p1i * 128 + lr];
    float inv = 1.0f / l;
    float ox = (O0.x + O1.x) * inv;
    float oy = (O0.y + O1.y) * inv;

    u32 hp, lp;
    split_pack(ox, oy, hp, lp);
    __nv_bfloat16* dst = g_x2 + ((long long)b * NT + n) * KP + h * HD + 2 * cp;
    *(u32*)(dst) = hp;
    *(u32*)(dst + 1024) = hp;
    *(u32*)(dst + 2048) = lp;
}

// ---------------------------------------------------------------------------
// Launch
// ---------------------------------------------------------------------------
extern "C" void kernel_launch(void* const* d_in, const int* in_sizes, int n_in,
                              void* d_out, int out_size)
{
    const float* x1  = (const float*)d_in[0];
    const float* x2  = (const float*)d_in[1];
    const float* Wq1 = (const float*)d_in[2];
    const float* bq1 = (const float*)d_in[3];
    const float* Wq2 = (const float*)d_in[4];
    const float* bq2 = (const float*)d_in[5];
    const float* Wo1 = (const float*)d_in[6];
    const float* bo1 = (const float*)d_in[7];
    const float* Wo2 = (const float*)d_in[8];
    const float* bo2 = (const float*)d_in[9];
    const float* qs1 = (const float*)d_in[10];
    const float* ks1 = (const float*)d_in[11];
    const float* qs2 = (const float*)d_in[12];
    const float* ks2 = (const float*)d_in[13];
    float* out = (float*)d_out;

    float* qkv;
    cudaGetSymbolAddress((void**)&qkv, g_qkv);
    __nv_bfloat16 *a1, *a2, *x2b, *w1, *w2, *o1, *o2;
    cudaGetSymbolAddress((void**)&a1, g_a1);
    cudaGetSymbolAddress((void**)&a2, g_a2);
    cudaGetSymbolAddress((void**)&x2b, g_x2);
    cudaGetSymbolAddress((void**)&w1, g_w1);
    cudaGetSymbolAddress((void**)&w2, g_w2);
    cudaGetSymbolAddress((void**)&o1, g_o1);
    cudaGetSymbolAddress((void**)&o2, g_o2);

    cudaFuncSetAttribute(flash_attn, cudaFuncAttributeMaxDynamicSharedMemorySize,
                         FA_SMEM);
    cudaFuncSetAttribute(gemm_mma2, cudaFuncAttributeMaxDynamicSharedMemorySize,
                         GSMEM);

    // --- ALL bf16 split conversions in one launch ---
    cvt_all<<<2048, 256>>>((const float4*)x1, (const float4*)x2,
                           (const float4*)Wq1, (const float4*)Wq2,
                           (const float4*)Wo1, (const float4*)Wo2,
                           a1, a2, w1, w2, o1, o2);

    // --- QKV projections, both segments in ONE launch ---
    gemm_mma2<<<dim3(24, 32), 256, GSMEM>>>(
        a1, w1, bq1, qkv,
        3072, 3072, NSEG1, (long long)NT * 3 * DM,
        a2, w2, bq2, qkv + (long long)NSEG1 * 3 * DM,
        1024, 1024, NSEG2, (long long)NT * 3 * DM,
        3072, 24);

    // --- split + RMSNorm + RoPE -> bf16 hi/lo operands ---
    qkv_post<<<(BATCH * NT * NH) / 8, 256>>>(qs1, ks1, qs2, ks2);

    // --- attention: split-KV partials, then merge ---
    flash_attn<<<dim3(16, NH, BATCH * 2), 256, FA_SMEM>>>();
    merge_attn<<<(BATCH * NT * NH * 32) / 256, 256>>>();

    // --- output projections, both segments in ONE launch ---
    gemm_mma2<<<dim3(8, 32), 256, GSMEM>>>(
        x2b, o1, bo1, out,
        1536, 2048, NSEG1, (long long)NSEG1 * DM,
        x2b + (long long)NSEG1 * KP, o2, bo2, out + (long long)BATCH * NSEG1 * DM,
        512, 2048, NSEG2, (long long)NSEG2 * DM,
        1024, 24);
}